// round 16
// baseline (speedup 1.0000x reference)
#include <cuda_runtime.h>
#include <cuda_fp16.h>
#include <cstdint>

#define B_Q   256
#define N_MEM 50000
#define D_DIM 1024
#define NTILE 256
#define KC    64                             // f16 elements per chunk (128B row)
#define NCHUNK (D_DIM / KC)                  // 16
#define NBLK  ((N_MEM + NTILE - 1) / NTILE)  // 196

// SMEM (dynamic): double-buffered Q and M (both 256 rows x 128B)
#define SM_Q     0                       // 2 x 32KB
#define SM_M     65536                   // 2 x 32KB
#define SM_NORM  (SM_M + 65536)          // 256 floats
#define SMEM_TOTAL (SM_NORM + 1024)

__device__ unsigned long long g_best[B_Q];
__device__ __half g_qh[B_Q * D_DIM];

__device__ __forceinline__ uint32_t smem_u32(const void* p) {
    uint32_t a;
    asm("{ .reg .u64 t; cvta.to.shared.u64 t, %1; cvt.u32.u64 %0, t; }" : "=r"(a) : "l"(p));
    return a;
}
__device__ __forceinline__ unsigned int fkey(float f) {
    unsigned int u = __float_as_uint(f);
    return (u & 0x80000000u) ? ~u : (u | 0x80000000u);
}
#define SW128(off) ((off) ^ (((off) >> 3) & 0x70))

#define LDSM_X4(r0, r1, r2, r3, a) \
    asm volatile("ldmatrix.sync.aligned.m8n8.x4.shared.b16 {%0,%1,%2,%3}, [%4];" \
                 : "=r"(r0), "=r"(r1), "=r"(r2), "=r"(r3) : "r"(a))
#define LDSM_X4_T(r0, r1, r2, r3, a) \
    asm volatile("ldmatrix.sync.aligned.m8n8.x4.trans.shared.b16 {%0,%1,%2,%3}, [%4];" \
                 : "=r"(r0), "=r"(r1), "=r"(r2), "=r"(r3) : "r"(a))
#define MMA_F16(d, a, b0, b1) \
    asm volatile("mma.sync.aligned.m16n8k16.row.col.f16.f16.f16.f16 " \
                 "{%0,%1}, {%2,%3,%4,%5}, {%6,%7}, {%0,%1};" \
                 : "+r"((d)[0]), "+r"((d)[1]) \
                 : "r"((a)[0]), "r"((a)[1]), "r"((a)[2]), "r"((a)[3]), "r"(b0), "r"(b1))

__device__ __forceinline__ uint32_t pack_h2(float x, float y) {
    __half2 h = __floats2half2_rn(x, y);
    return *reinterpret_cast<uint32_t*>(&h);
}

// Q fp32 -> f16 once; reset g_best.
__global__ __launch_bounds__(256) void prep_kernel(const float* __restrict__ Q) {
    int idx = blockIdx.x * 256 + threadIdx.x;
    const float4 v = reinterpret_cast<const float4*>(Q)[idx];
    uint2 w;
    w.x = pack_h2(v.x, v.y);
    w.y = pack_h2(v.z, v.w);
    reinterpret_cast<uint2*>(g_qh)[idx] = w;
    if (blockIdx.x == 0) g_best[threadIdx.x] = 0ull;
}

// f16 GEMM (256q x 256n x 1024k), f16 acc, fused norms + argmax.
// 512 thr, 16 warps (4wq x 4wn), warp tile 64q x 64n, double buffer,
// packed-register M prefetch, 1 sync/chunk, prefetch-before-barrier.
__global__ __launch_bounds__(512, 1) void simmax_mma(const float* __restrict__ Mptr) {
    extern __shared__ char smem[];
    const uint32_t sb = smem_u32(smem);
    const int tid = threadIdx.x;
    const int l   = tid & 31;
    const int wid = tid >> 5;
    const int wq  = wid >> 2;          // 0..3 : q block of 64
    const int wn  = wid & 3;           // 0..3 : n block of 64
    const int ntile = blockIdx.x * NTILE;

    float* norms = reinterpret_cast<float*>(smem + SM_NORM);

    uint32_t acc[4][8][2];             // f16x2 accumulators (64q x 64n per warp)
#pragma unroll
    for (int mt = 0; mt < 4; mt++)
#pragma unroll
        for (int nt = 0; nt < 8; nt++) {
            acc[mt][nt][0] = 0u;
            acc[mt][nt][1] = 0u;
        }

    // ---- M loader: 2048 16B f16-segs/chunk (256 rows x 8), 4/thread.
    //      Loaded as 2 float4 (8 fp32) -> packed uint4 at prefetch time.
    const int mcol = tid & 7;                       // col seg (8 f16 / 32B fp32)
    int  mrow[4];
    bool mok[4];
    const float* msrc[4];
#pragma unroll
    for (int i = 0; i < 4; i++) {
        mrow[i] = (tid >> 3) + 64 * i;
        int gn = ntile + mrow[i];
        mok[i] = (gn < N_MEM);
        msrc[i] = Mptr + (size_t)gn * D_DIM + mcol * 8;
    }
    uint4 mq[4];                                    // packed f16 prefetch
    float ss[4] = {0.f, 0.f, 0.f, 0.f};             // per-row sumsq partials (fp32)

    // ---- Q loader: 2048 16B segs/chunk, 4/thread
    const int qrow = tid >> 3;                      // NOTE: same row map as M group 0
    const int qcol = tid & 7;
    uint4 qq[4];
    const __half* qsrcb = g_qh + qcol * 8;

    auto load_m = [&](int c) {
#pragma unroll
        for (int i = 0; i < 4; i++) {
            float4 f0 = make_float4(0,0,0,0), f1 = make_float4(0,0,0,0);
            if (mok[i]) {
                f0 = *reinterpret_cast<const float4*>(msrc[i] + c * KC);
                f1 = *reinterpret_cast<const float4*>(msrc[i] + c * KC + 4);
            }
            ss[i] += f0.x*f0.x + f0.y*f0.y + f0.z*f0.z + f0.w*f0.w
                   + f1.x*f1.x + f1.y*f1.y + f1.z*f1.z + f1.w*f1.w;
            mq[i].x = pack_h2(f0.x, f0.y);
            mq[i].y = pack_h2(f0.z, f0.w);
            mq[i].z = pack_h2(f1.x, f1.y);
            mq[i].w = pack_h2(f1.z, f1.w);
        }
    };
    auto load_q = [&](int c) {
#pragma unroll
        for (int i = 0; i < 4; i++)
            qq[i] = *reinterpret_cast<const uint4*>(
                qsrcb + (size_t)(qrow + 64 * i) * D_DIM + c * KC);
    };

    // ---- prologue: chunk 0
    load_m(0);
    load_q(0);

    const int lrow = l & 15;
    const int lhi  = (l >> 4) * 16;

    for (int c = 0; c < NCHUNK; c++) {
        const int slot = c & 1;
        const uint32_t qb = (uint32_t)(SM_Q + slot * 32768);
        const uint32_t mb = (uint32_t)(SM_M + slot * 32768);

        // ---- STS chunk c from packed regs
#pragma unroll
        for (int i = 0; i < 4; i++) {
            uint32_t qoff = (uint32_t)((qrow + 64 * i) * 128 + qcol * 16);
            *reinterpret_cast<uint4*>(smem + qb + SW128(qoff)) = qq[i];
            uint32_t moff = (uint32_t)(mrow[i] * 128 + mcol * 16);
            *reinterpret_cast<uint4*>(smem + mb + SW128(moff)) = mq[i];
        }

        // ---- prefetch chunk c+1 BEFORE the barrier (LDGs fly during skew)
        if (c + 1 < NCHUNK) {
            load_m(c + 1);
            load_q(c + 1);
        }
        __syncthreads();   // chunk c visible; orders compute(c-1) before buffer reuse

        // ---- compute chunk c: 4 k16 steps, 32 MMA each
#pragma unroll
        for (int ks = 0; ks < 4; ks++) {
            uint32_t b[4][4];
#pragma unroll
            for (int p = 0; p < 4; p++) {
                uint32_t off = (uint32_t)((wn * 64 + p * 16 + lrow) * 128 + ks * 32 + lhi);
                LDSM_X4_T(b[p][0], b[p][1], b[p][2], b[p][3], sb + mb + SW128(off));
            }
#pragma unroll
            for (int mt = 0; mt < 4; mt++) {
                uint32_t a[4];
                uint32_t off = (uint32_t)((wq * 64 + mt * 16 + lrow) * 128 + ks * 32 + lhi);
                LDSM_X4(a[0], a[1], a[2], a[3], sb + qb + SW128(off));
#pragma unroll
                for (int nt = 0; nt < 8; nt++)
                    MMA_F16(acc[mt][nt], a, b[nt >> 1][nt & 1], b[nt >> 1][(nt & 1) + 2]);
            }
        }
        // no trailing sync: next iteration's STS targets the other buffer.
    }

    // ---- row norms: 8 lanes per row (consecutive tids), fp32 exact
#pragma unroll
    for (int i = 0; i < 4; i++) {
        float v = ss[i];
        v += __shfl_xor_sync(0xFFFFFFFFu, v, 1);
        v += __shfl_xor_sync(0xFFFFFFFFu, v, 2);
        v += __shfl_xor_sync(0xFFFFFFFFu, v, 4);
        if (mcol == 0) norms[mrow[i]] = rsqrtf(fmaxf(v, 1e-30f));
    }
    __syncthreads();
    const float* invn = norms;

    // ---- epilogue: per-q-row argmax over this CTA's 256 n
#pragma unroll
    for (int mt = 0; mt < 4; mt++) {
#pragma unroll
        for (int sub = 0; sub < 2; sub++) {
            unsigned long long best = 0ull;
#pragma unroll
            for (int nt = 0; nt < 8; nt++) {
                __half2 h = *reinterpret_cast<__half2*>(&acc[mt][nt][sub]);
                float2 fv = __half22float2(h);
#pragma unroll
                for (int cc = 0; cc < 2; cc++) {
                    int nl = wn * 64 + nt * 8 + 2 * (l & 3) + cc;
                    int n = ntile + nl;
                    if (n < N_MEM) {
                        float s = (cc == 0 ? fv.x : fv.y) * invn[nl];
                        unsigned long long key =
                            ((unsigned long long)fkey(s) << 32) |
                            (unsigned long long)(unsigned int)(~(unsigned int)n);
                        if (key > best) best = key;
                    }
                }
            }
            unsigned long long o;
            o = __shfl_xor_sync(0xFFFFFFFFu, best, 1); if (o > best) best = o;
            o = __shfl_xor_sync(0xFFFFFFFFu, best, 2); if (o > best) best = o;
            if ((l & 3) == 0) {
                int q = wq * 64 + mt * 16 + (l >> 2) + sub * 8;
                atomicMax(&g_best[q], best);
            }
        }
    }
}

// Fused: exact fp32 re-verify of the winner + threshold + decode.
__global__ __launch_bounds__(512) void final_decode_kernel(const float* __restrict__ Q,
                                                           const float* __restrict__ M,
                                                           const float* __restrict__ W,
                                                           const float* __restrict__ bias,
                                                           float* __restrict__ out) {
    __shared__ float sdq[512], sdm[512], sdp[512];
    __shared__ int s_sel;
    const int b = blockIdx.y;
    const int tid = threadIdx.x;

    unsigned long long pk = g_best[b];
    const int idx = (int)(~(unsigned int)(pk & 0xFFFFFFFFull));

    const float* q = Q + (size_t)b * D_DIM;
    const float* m = M + (size_t)idx * D_DIM;
    {
        float2 qa = *reinterpret_cast<const float2*>(&q[tid * 2]);
        float2 mb = *reinterpret_cast<const float2*>(&m[tid * 2]);
        sdq[tid] = qa.x * qa.x + qa.y * qa.y;
        sdm[tid] = mb.x * mb.x + mb.y * mb.y;
        sdp[tid] = qa.x * mb.x + qa.y * mb.y;
    }
    __syncthreads();
    for (int s = 256; s > 0; s >>= 1) {
        if (tid < s) {
            sdq[tid] += sdq[tid + s];
            sdm[tid] += sdm[tid + s];
            sdp[tid] += sdp[tid + s];
        }
        __syncthreads();
    }
    if (tid == 0) {
        float sim = sdp[0] / fmaxf(sqrtf(sdq[0]) * sqrtf(sdm[0]), 1e-8f);
        s_sel = (sim > 0.6f) ? idx : -1;
    }
    __syncthreads();

    const int sel = s_sel;
    const int j = blockIdx.x * 512 + tid;
    float r = 0.0f;
    if (sel >= 0) {
        const float* e = M + (size_t)sel * D_DIM;
        const float* w = W + (size_t)j * D_DIM;
        float s = 0.0f;
        for (int k = 0; k < D_DIM; k += 4) {
            float4 ev = *reinterpret_cast<const float4*>(&e[k]);
            float4 wv = *reinterpret_cast<const float4*>(&w[k]);
            s += ev.x * wv.x + ev.y * wv.y + ev.z * wv.z + ev.w * wv.w;
        }
        r = s + bias[j];
    }
    out[(size_t)b * D_DIM + j] = r;
}

extern "C" void kernel_launch(void* const* d_in, const int* in_sizes, int n_in,
                              void* d_out, int out_size) {
    const float* Q    = (const float*)d_in[0];
    const float* M    = (const float*)d_in[1];
    const float* W    = (const float*)d_in[2];
    const float* bias = (const float*)d_in[3];
    float* out = (float*)d_out;

    cudaFuncSetAttribute(simmax_mma, cudaFuncAttributeMaxDynamicSharedMemorySize, SMEM_TOTAL);

    prep_kernel<<<B_Q * D_DIM / 4 / 256, 256>>>(Q);
    simmax_mma<<<NBLK, 512, SMEM_TOTAL>>>(M);
    final_decode_kernel<<<dim3(D_DIM / 512, B_Q), 512>>>(Q, M, W, bias, out);
}

// round 17
// speedup vs baseline: 1.3672x; 1.3672x over previous
#include <cuda_runtime.h>
#include <cuda_fp16.h>
#include <cstdint>

#define B_Q   256
#define N_MEM 50000
#define D_DIM 1024
#define NTILE 128
#define KC    128                            // f16 k per super-chunk (2 x 64 slabs)
#define NCHUNK (D_DIM / KC)                  // 8
#define NBLK  ((N_MEM + NTILE - 1) / NTILE)  // 391

// SMEM (dynamic): double-buffered; buffer = 2 slabs of (Q 32KB + M 16KB)
#define SM_Q     0                       // 2 buf x 64KB = 128KB
#define SM_M     131072                  // 2 buf x 32KB = 64KB
#define SM_NORM  (SM_M + 65536)          // 128 floats
#define SMEM_TOTAL (SM_NORM + 512)

__device__ unsigned long long g_best[B_Q];
__device__ __half g_qh[B_Q * D_DIM];

__device__ __forceinline__ uint32_t smem_u32(const void* p) {
    uint32_t a;
    asm("{ .reg .u64 t; cvta.to.shared.u64 t, %1; cvt.u32.u64 %0, t; }" : "=r"(a) : "l"(p));
    return a;
}
__device__ __forceinline__ unsigned int fkey(float f) {
    unsigned int u = __float_as_uint(f);
    return (u & 0x80000000u) ? ~u : (u | 0x80000000u);
}
#define SW128(off) ((off) ^ (((off) >> 3) & 0x70))

#define LDSM_X4(r0, r1, r2, r3, a) \
    asm volatile("ldmatrix.sync.aligned.m8n8.x4.shared.b16 {%0,%1,%2,%3}, [%4];" \
                 : "=r"(r0), "=r"(r1), "=r"(r2), "=r"(r3) : "r"(a))
#define LDSM_X4_T(r0, r1, r2, r3, a) \
    asm volatile("ldmatrix.sync.aligned.m8n8.x4.trans.shared.b16 {%0,%1,%2,%3}, [%4];" \
                 : "=r"(r0), "=r"(r1), "=r"(r2), "=r"(r3) : "r"(a))
#define MMA_F16(d, a, b0, b1) \
    asm volatile("mma.sync.aligned.m16n8k16.row.col.f16.f16.f16.f16 " \
                 "{%0,%1}, {%2,%3,%4,%5}, {%6,%7}, {%0,%1};" \
                 : "+r"((d)[0]), "+r"((d)[1]) \
                 : "r"((a)[0]), "r"((a)[1]), "r"((a)[2]), "r"((a)[3]), "r"(b0), "r"(b1))

__device__ __forceinline__ uint32_t pack_h2(float x, float y) {
    __half2 h = __floats2half2_rn(x, y);
    return *reinterpret_cast<uint32_t*>(&h);
}

// Q fp32 -> f16 once; reset g_best.
__global__ __launch_bounds__(256) void prep_kernel(const float* __restrict__ Q) {
    int idx = blockIdx.x * 256 + threadIdx.x;
    const float4 v = reinterpret_cast<const float4*>(Q)[idx];
    uint2 w;
    w.x = pack_h2(v.x, v.y);
    w.y = pack_h2(v.z, v.w);
    reinterpret_cast<uint2*>(g_qh)[idx] = w;
    if (blockIdx.x == 0) g_best[threadIdx.x] = 0ull;
}

// f16 GEMM (256q x 128n x 1024k), f16 acc, fused norms + argmax.
// r15 body, super-chunked KC=128 with REGISTER staging (no cp.async):
// 8 syncs/CTA, 512 thr, 16 warps (4wq x 4wn), 64q x 32n warp tile.
__global__ __launch_bounds__(512, 1) void simmax_mma(const float* __restrict__ Mptr) {
    extern __shared__ char smem[];
    const uint32_t sb = smem_u32(smem);
    const int tid = threadIdx.x;
    const int l   = tid & 31;
    const int wid = tid >> 5;
    const int wq  = wid >> 2;          // 0..3 : q block of 64
    const int wn  = wid & 3;           // 0..3 : n block of 32
    const int ntile = blockIdx.x * NTILE;

    float* norms = reinterpret_cast<float*>(smem + SM_NORM);

    uint32_t acc[4][4][2];             // f16x2 accumulators (64q x 32n per warp)
#pragma unroll
    for (int mt = 0; mt < 4; mt++)
#pragma unroll
        for (int nt = 0; nt < 4; nt++) {
            acc[mt][nt][0] = 0u;
            acc[mt][nt][1] = 0u;
        }

    // ---- Q loader: per super-chunk 4096 16B segs (2 slabs x 2048); 8/thread
    //      qq[i]: slab h = i>>2, s = tid + 512*(i&3), row = s>>3, col = s&7
    const int qrow = tid >> 3;         // base row for i&3==0 (rows advance by 64)
    const int qcol = tid & 7;
    uint4 qq[8];

    // ---- M loader: per super-chunk 2048 segs (2 slabs x 1024); 4/thread packed
    //      mq[i]: slab h = i>>1, s = tid + 512*(i&1), row = s>>3, col = s&7
    const int mcol = tid & 7;
    int  mrowb[2];
    bool mok[2];
    const float* msrc[2];
#pragma unroll
    for (int j = 0; j < 2; j++) {
        mrowb[j] = ((tid + 512 * j) >> 3) & 127;   // rows 0..127 (tid<1024 so fine)
        int gn = ntile + mrowb[j];
        mok[j] = (gn < N_MEM);
        msrc[j] = Mptr + (size_t)gn * D_DIM + mcol * 8;
    }
    uint4 mq[4];
    float ss[2] = {0.f, 0.f};

    auto load_q = [&](int c) {
#pragma unroll
        for (int i = 0; i < 8; i++) {
            int h = i >> 2;
            int row = qrow + 64 * (i & 3);
            qq[i] = *reinterpret_cast<const uint4*>(
                g_qh + (size_t)row * D_DIM + c * KC + h * 64 + qcol * 8);
        }
    };
    auto load_m = [&](int c) {
#pragma unroll
        for (int i = 0; i < 4; i++) {
            int h = i >> 1, j = i & 1;
            float4 f0 = make_float4(0,0,0,0), f1 = make_float4(0,0,0,0);
            if (mok[j]) {
                f0 = *reinterpret_cast<const float4*>(msrc[j] + c * KC + h * 64);
                f1 = *reinterpret_cast<const float4*>(msrc[j] + c * KC + h * 64 + 4);
            }
            ss[j] += f0.x*f0.x + f0.y*f0.y + f0.z*f0.z + f0.w*f0.w
                   + f1.x*f1.x + f1.y*f1.y + f1.z*f1.z + f1.w*f1.w;
            mq[i].x = pack_h2(f0.x, f0.y);
            mq[i].y = pack_h2(f0.z, f0.w);
            mq[i].z = pack_h2(f1.x, f1.y);
            mq[i].w = pack_h2(f1.z, f1.w);
        }
    };

    // ---- prologue: super-chunk 0
    load_q(0);
    load_m(0);

    const int lrow = l & 15;
    const int lhi  = (l >> 4) * 16;

    for (int c = 0; c < NCHUNK; c++) {
        const int slot = c & 1;
        const uint32_t qbuf = (uint32_t)(SM_Q + slot * 65536);
        const uint32_t mbuf = (uint32_t)(SM_M + slot * 32768);

        // ---- STS super-chunk c from regs
#pragma unroll
        for (int i = 0; i < 8; i++) {
            int h = i >> 2;
            uint32_t off = (uint32_t)((qrow + 64 * (i & 3)) * 128 + qcol * 16);
            *reinterpret_cast<uint4*>(smem + qbuf + h * 32768 + SW128(off)) = qq[i];
        }
#pragma unroll
        for (int i = 0; i < 4; i++) {
            int h = i >> 1, j = i & 1;
            uint32_t off = (uint32_t)(mrowb[j] * 128 + mcol * 16);
            *reinterpret_cast<uint4*>(smem + mbuf + h * 16384 + SW128(off)) = mq[i];
        }

        // ---- prefetch super-chunk c+1 BEFORE the barrier
        if (c + 1 < NCHUNK) {
            load_q(c + 1);
            load_m(c + 1);
        }
        __syncthreads();   // chunk c visible; orders compute(c-1) before buffer reuse

        // ---- compute super-chunk c: 2 slabs x 4 k16 steps
#pragma unroll
        for (int h = 0; h < 2; h++) {
            const uint32_t qb = qbuf + h * 32768;
            const uint32_t mb = mbuf + h * 16384;
#pragma unroll
            for (int ks = 0; ks < 4; ks++) {
                uint32_t b[2][4];
#pragma unroll
                for (int p = 0; p < 2; p++) {
                    uint32_t off = (uint32_t)((wn * 32 + p * 16 + lrow) * 128 + ks * 32 + lhi);
                    LDSM_X4_T(b[p][0], b[p][1], b[p][2], b[p][3], sb + mb + SW128(off));
                }
#pragma unroll
                for (int mt = 0; mt < 4; mt++) {
                    uint32_t a[4];
                    uint32_t off = (uint32_t)((wq * 64 + mt * 16 + lrow) * 128 + ks * 32 + lhi);
                    LDSM_X4(a[0], a[1], a[2], a[3], sb + qb + SW128(off));
#pragma unroll
                    for (int nt = 0; nt < 4; nt++)
                        MMA_F16(acc[mt][nt], a, b[nt >> 1][nt & 1], b[nt >> 1][(nt & 1) + 2]);
                }
            }
        }
        // no trailing sync: next iteration targets the other buffer.
    }

    // ---- row norms: 8 lanes per row (consecutive tids), fp32 exact
#pragma unroll
    for (int j = 0; j < 2; j++) {
        float v = ss[j];
        v += __shfl_xor_sync(0xFFFFFFFFu, v, 1);
        v += __shfl_xor_sync(0xFFFFFFFFu, v, 2);
        v += __shfl_xor_sync(0xFFFFFFFFu, v, 4);
        if (mcol == 0) norms[mrowb[j]] = rsqrtf(fmaxf(v, 1e-30f));
    }
    __syncthreads();
    const float* invn = norms;

    // ---- epilogue: per-q-row argmax over this CTA's 128 n
#pragma unroll
    for (int mt = 0; mt < 4; mt++) {
#pragma unroll
        for (int sub = 0; sub < 2; sub++) {
            unsigned long long best = 0ull;
#pragma unroll
            for (int nt = 0; nt < 4; nt++) {
                __half2 h = *reinterpret_cast<__half2*>(&acc[mt][nt][sub]);
                float2 fv = __half22float2(h);
#pragma unroll
                for (int cc = 0; cc < 2; cc++) {
                    int nl = wn * 32 + nt * 8 + 2 * (l & 3) + cc;
                    int n = ntile + nl;
                    if (n < N_MEM) {
                        float s = (cc == 0 ? fv.x : fv.y) * invn[nl];
                        unsigned long long key =
                            ((unsigned long long)fkey(s) << 32) |
                            (unsigned long long)(unsigned int)(~(unsigned int)n);
                        if (key > best) best = key;
                    }
                }
            }
            unsigned long long o;
            o = __shfl_xor_sync(0xFFFFFFFFu, best, 1); if (o > best) best = o;
            o = __shfl_xor_sync(0xFFFFFFFFu, best, 2); if (o > best) best = o;
            if ((l & 3) == 0) {
                int q = wq * 64 + mt * 16 + (l >> 2) + sub * 8;
                atomicMax(&g_best[q], best);
            }
        }
    }
}

// Fused: exact fp32 re-verify of the winner + threshold + decode.
__global__ __launch_bounds__(512) void final_decode_kernel(const float* __restrict__ Q,
                                                           const float* __restrict__ M,
                                                           const float* __restrict__ W,
                                                           const float* __restrict__ bias,
                                                           float* __restrict__ out) {
    __shared__ float sdq[512], sdm[512], sdp[512];
    __shared__ int s_sel;
    const int b = blockIdx.y;
    const int tid = threadIdx.x;

    unsigned long long pk = g_best[b];
    const int idx = (int)(~(unsigned int)(pk & 0xFFFFFFFFull));

    const float* q = Q + (size_t)b * D_DIM;
    const float* m = M + (size_t)idx * D_DIM;
    {
        float2 qa = *reinterpret_cast<const float2*>(&q[tid * 2]);
        float2 mb = *reinterpret_cast<const float2*>(&m[tid * 2]);
        sdq[tid] = qa.x * qa.x + qa.y * qa.y;
        sdm[tid] = mb.x * mb.x + mb.y * mb.y;
        sdp[tid] = qa.x * mb.x + qa.y * mb.y;
    }
    __syncthreads();
    for (int s = 256; s > 0; s >>= 1) {
        if (tid < s) {
            sdq[tid] += sdq[tid + s];
            sdm[tid] += sdm[tid + s];
            sdp[tid] += sdp[tid + s];
        }
        __syncthreads();
    }
    if (tid == 0) {
        float sim = sdp[0] / fmaxf(sqrtf(sdq[0]) * sqrtf(sdm[0]), 1e-8f);
        s_sel = (sim > 0.6f) ? idx : -1;
    }
    __syncthreads();

    const int sel = s_sel;
    const int j = blockIdx.x * 512 + tid;
    float r = 0.0f;
    if (sel >= 0) {
        const float* e = M + (size_t)sel * D_DIM;
        const float* w = W + (size_t)j * D_DIM;
        float s = 0.0f;
        for (int k = 0; k < D_DIM; k += 4) {
            float4 ev = *reinterpret_cast<const float4*>(&e[k]);
            float4 wv = *reinterpret_cast<const float4*>(&w[k]);
            s += ev.x * wv.x + ev.y * wv.y + ev.z * wv.z + ev.w * wv.w;
        }
        r = s + bias[j];
    }
    out[(size_t)b * D_DIM + j] = r;
}

extern "C" void kernel_launch(void* const* d_in, const int* in_sizes, int n_in,
                              void* d_out, int out_size) {
    const float* Q    = (const float*)d_in[0];
    const float* M    = (const float*)d_in[1];
    const float* W    = (const float*)d_in[2];
    const float* bias = (const float*)d_in[3];
    float* out = (float*)d_out;

    cudaFuncSetAttribute(simmax_mma, cudaFuncAttributeMaxDynamicSharedMemorySize, SMEM_TOTAL);

    prep_kernel<<<B_Q * D_DIM / 4 / 256, 256>>>(Q);
    simmax_mma<<<NBLK, 512, SMEM_TOTAL>>>(M);
    final_decode_kernel<<<dim3(D_DIM / 512, B_Q), 512>>>(Q, M, W, bias, out);
}